// round 7
// baseline (speedup 1.0000x reference)
#include <cuda_runtime.h>
#include <cuda_bf16.h>
#include <cstdint>

#define N_NODES 50000
#define N_EDGES 600000
#define D_FEAT  128
#define OUT_DIM 128

#define SCAN_BLK 512
#define N_SCAN_BLKS ((N_NODES + SCAN_BLK - 1) / SCAN_BLK)   // 98

#define BM  64                       // gemm rows per block
#define KQ  64                       // k-quarter
#define N_GEMM_BLKS ((N_NODES + BM - 1) / BM)   // 782
#define FUSED_SMEM ((KQ * OUT_DIM + BM * KQ) * 4)  // 32768 + 16384 = 49152

#define N_GATHER_BLKS ((N_NODES + 7) / 8)       // 6250 (8 nodes per block)
#define FUSED_GRID (N_GEMM_BLKS + N_GATHER_BLKS)  // 7032; every 9th block = gemm

// ---------------------------------------------------------------------------
// Scratch (static device globals)
// ---------------------------------------------------------------------------
__device__ int g_cnt_i [N_NODES];
__device__ int g_cursor[N_NODES];
__device__ int g_off   [N_NODES];
__device__ int g_btot  [N_SCAN_BLKS];
__device__ int g_eid   [N_EDGES];
__device__ __align__(16) float g_agg[N_NODES * D_FEAT];   // 25.6 MB

// ---------------------------------------------------------------------------
// Kernel 1: zero counters
// ---------------------------------------------------------------------------
__global__ void zero_counters_kernel() {
    int i = blockIdx.x * blockDim.x + threadIdx.x;
    if (i < N_NODES) { g_cnt_i[i] = 0; g_cursor[i] = 0; }
}

// ---------------------------------------------------------------------------
// Kernel 2: histogram of destination nodes
// ---------------------------------------------------------------------------
__global__ void count_kernel(const int* __restrict__ src_idx) {
    int e = blockIdx.x * blockDim.x + threadIdx.x;
    if (e < N_EDGES) atomicAdd(&g_cnt_i[src_idx[e]], 1);
}

// ---------------------------------------------------------------------------
// Kernel 3: per-block exclusive scan; block totals to g_btot
// ---------------------------------------------------------------------------
__global__ __launch_bounds__(SCAN_BLK)
void scan_partial_kernel() {
    __shared__ int sh[SCAN_BLK];
    const int tid = threadIdx.x;
    const int i   = blockIdx.x * SCAN_BLK + tid;
    const int v   = (i < N_NODES) ? g_cnt_i[i] : 0;
    sh[tid] = v;
    __syncthreads();
    #pragma unroll
    for (int d = 1; d < SCAN_BLK; d <<= 1) {
        int t = (tid >= d) ? sh[tid - d] : 0;
        __syncthreads();
        sh[tid] += t;
        __syncthreads();
    }
    if (i < N_NODES) g_off[i] = sh[tid] - v;
    if (tid == SCAN_BLK - 1) g_btot[blockIdx.x] = sh[tid];
}

// ---------------------------------------------------------------------------
// Inline 98-element exclusive prefix of g_btot into smem (all threads of the
// block participate in syncs; threads 0..127 do the work). ~200 cyc.
// ---------------------------------------------------------------------------
__device__ __forceinline__ void boff_scan(int* sb) {
    const int tid = threadIdx.x;
    int v = 0;
    if (tid < 128) {
        v = (tid < N_SCAN_BLKS) ? g_btot[tid] : 0;
        sb[tid] = v;
    }
    __syncthreads();
    #pragma unroll
    for (int d = 1; d < 128; d <<= 1) {
        int x = (tid < 128 && tid >= d) ? sb[tid - d] : 0;
        __syncthreads();
        if (tid < 128) sb[tid] += x;
        __syncthreads();
    }
    if (tid < 128) sb[tid] -= v;   // exclusive
    __syncthreads();
}

// ---------------------------------------------------------------------------
// Kernel 4: scatter edge ids into destination-sorted order (boff inlined)
// ---------------------------------------------------------------------------
__global__ __launch_bounds__(256)
void scatter_ids_kernel(const int* __restrict__ src_idx) {
    __shared__ int sb[128];
    boff_scan(sb);
    int e = blockIdx.x * blockDim.x + threadIdx.x;
    if (e < N_EDGES) {
        const int s = src_idx[e];
        const int pos = g_off[s] + sb[s >> 9] + atomicAdd(&g_cursor[s], 1);
        g_eid[pos] = e;
    }
}

// ---------------------------------------------------------------------------
// GEMM tile (shared by fused half0 and half1): 64 rows x 128 cols, K=128
// processed as two K-quarters of 64 so smem = 48KB -> 4 blocks/SM.
// Thread t: cols j0=(t%32)*4, rows r0=(t/32)*8; packed fma.rn.f32x2.
// ---------------------------------------------------------------------------
__device__ __forceinline__ void gemm_tile(const float* __restrict__ xsrc,
                                          const float* __restrict__ Wq0,
                                          float*       __restrict__ out,
                                          int n0, float* sh, bool addout) {
    float* Wsh = sh;                // [KQ][OUT_DIM] 32KB
    float* Xsh = sh + KQ * OUT_DIM; // [BM][KQ]      16KB
    const int tid = threadIdx.x;

    const int j0 = (tid & 31) * 4;
    const int r0 = (tid >> 5) * 8;

    unsigned long long a01[8], a23[8];
    #pragma unroll
    for (int r = 0; r < 8; ++r) { a01[r] = 0ull; a23[r] = 0ull; }

    #pragma unroll
    for (int q = 0; q < 2; ++q) {
        if (q) __syncthreads();
        // W quarter: 64x128 floats = 2048 float4
        {
            const float4* W4 = reinterpret_cast<const float4*>(Wq0 + q * KQ * OUT_DIM);
            float4* Wsh4 = reinterpret_cast<float4*>(Wsh);
            #pragma unroll
            for (int i = tid; i < KQ * OUT_DIM / 4; i += 256) Wsh4[i] = W4[i];
        }
        // X quarter: 64 rows x 64 cols = 1024 float4
        {
            const float4* x4 = reinterpret_cast<const float4*>(xsrc);
            const float4  z  = make_float4(0.f, 0.f, 0.f, 0.f);
            #pragma unroll
            for (int i = tid; i < BM * (KQ / 4); i += 256) {
                const int r  = i / (KQ / 4);
                const int c4 = i % (KQ / 4);
                const int n  = n0 + r;
                float4 v = z;
                if (n < N_NODES)
                    v = x4[(size_t)n * (D_FEAT / 4) + q * (KQ / 4) + c4];
                reinterpret_cast<float4*>(&Xsh[r * KQ])[c4] = v;
            }
        }
        __syncthreads();

        #pragma unroll 2
        for (int k = 0; k < KQ; k += 2) {
            const unsigned long long wA0 =
                *reinterpret_cast<const unsigned long long*>(&Wsh[k * OUT_DIM + j0]);
            const unsigned long long wB0 =
                *reinterpret_cast<const unsigned long long*>(&Wsh[k * OUT_DIM + j0 + 2]);
            const unsigned long long wA1 =
                *reinterpret_cast<const unsigned long long*>(&Wsh[(k + 1) * OUT_DIM + j0]);
            const unsigned long long wB1 =
                *reinterpret_cast<const unsigned long long*>(&Wsh[(k + 1) * OUT_DIM + j0 + 2]);

            #pragma unroll
            for (int r = 0; r < 8; ++r) {
                const float2 x = *reinterpret_cast<const float2*>(&Xsh[(r0 + r) * KQ + k]);
                unsigned long long xx0, xx1;
                asm("mov.b64 %0, {%1, %1};" : "=l"(xx0) : "f"(x.x));
                asm("mov.b64 %0, {%1, %1};" : "=l"(xx1) : "f"(x.y));
                asm("fma.rn.f32x2 %0, %1, %2, %0;" : "+l"(a01[r]) : "l"(xx0), "l"(wA0));
                asm("fma.rn.f32x2 %0, %1, %2, %0;" : "+l"(a23[r]) : "l"(xx0), "l"(wB0));
                asm("fma.rn.f32x2 %0, %1, %2, %0;" : "+l"(a01[r]) : "l"(xx1), "l"(wA1));
                asm("fma.rn.f32x2 %0, %1, %2, %0;" : "+l"(a23[r]) : "l"(xx1), "l"(wB1));
            }
        }
    }

    #pragma unroll
    for (int r = 0; r < 8; ++r) {
        const int n = n0 + r0 + r;
        if (n < N_NODES) {
            float o0, o1, o2, o3;
            asm("mov.b64 {%0, %1}, %2;" : "=f"(o0), "=f"(o1) : "l"(a01[r]));
            asm("mov.b64 {%0, %1}, %2;" : "=f"(o2), "=f"(o3) : "l"(a23[r]));
            float4* po = reinterpret_cast<float4*>(&out[(size_t)n * OUT_DIM + j0]);
            if (addout) {
                const float4 prev = *po;
                *po = make_float4(prev.x + o0, prev.y + o1, prev.z + o2, prev.w + o3);
            } else {
                *po = make_float4(o0, o1, o2, o3);
            }
        }
    }
}

// ---------------------------------------------------------------------------
// Kernel 5 (fused): every 9th block = GEMM half0 (self_feat @ W[0:128] -> out),
// others = gather (one warp per node -> g_agg). DRAM-bound gather overlaps
// FMA-bound gemm within each wave.
// ---------------------------------------------------------------------------
__global__ __launch_bounds__(256, 4)
void fused_kernel(const float* __restrict__ self_feat,
                  const float* __restrict__ nbr_feat,
                  const float* __restrict__ W,
                  float*       __restrict__ out) {
    extern __shared__ float sh[];
    const int bid = blockIdx.x;

    if (bid % 9 == 0) {
        // ---- GEMM half0 role ----
        const int g = bid / 9;            // 0..781
        gemm_tile(self_feat, W, out, g * BM, sh, /*addout=*/false);
    } else {
        // ---- gather role ----
        int* sb = reinterpret_cast<int*>(sh);
        boff_scan(sb);

        const int gid  = (bid / 9) * 8 + (bid % 9) - 1;   // 0..6249
        const int wid  = threadIdx.x >> 5;
        const int lane = threadIdx.x & 31;
        const int node = gid * 8 + wid;
        if (node >= N_NODES) return;

        const int base = g_off[node] + sb[node >> 9];
        const int deg  = g_cnt_i[node];

        const float4* nb4 = reinterpret_cast<const float4*>(nbr_feat);
        float4 acc = make_float4(0.f, 0.f, 0.f, 0.f);

        int i = 0;
        if (deg >= 2) {
            int e0 = g_eid[base];
            int e1 = g_eid[base + 1];
            for (; i + 4 <= deg; i += 2) {
                const int ne0 = g_eid[base + i + 2];
                const int ne1 = g_eid[base + i + 3];
                const float4 v0 = nb4[(size_t)e0 * (D_FEAT / 4) + lane];
                const float4 v1 = nb4[(size_t)e1 * (D_FEAT / 4) + lane];
                acc.x += v0.x + v1.x;  acc.y += v0.y + v1.y;
                acc.z += v0.z + v1.z;  acc.w += v0.w + v1.w;
                e0 = ne0; e1 = ne1;
            }
            const float4 v0 = nb4[(size_t)e0 * (D_FEAT / 4) + lane];
            const float4 v1 = nb4[(size_t)e1 * (D_FEAT / 4) + lane];
            acc.x += v0.x + v1.x;  acc.y += v0.y + v1.y;
            acc.z += v0.z + v1.z;  acc.w += v0.w + v1.w;
            i += 2;
        }
        for (; i < deg; ++i) {
            const int e = g_eid[base + i];
            const float4 v = nb4[(size_t)e * (D_FEAT / 4) + lane];
            acc.x += v.x; acc.y += v.y; acc.z += v.z; acc.w += v.w;
        }

        const float s = (deg > 0) ? (1.0f / (float)deg) : 0.0f;
        acc.x *= s; acc.y *= s; acc.z *= s; acc.w *= s;
        reinterpret_cast<float4*>(g_agg)[(size_t)node * (D_FEAT / 4) + lane] = acc;
    }
}

// ---------------------------------------------------------------------------
// Kernel 6: GEMM half1 — out += g_agg @ W[128:256]
// ---------------------------------------------------------------------------
__global__ __launch_bounds__(256, 4)
void gemm_half1_kernel(const float* __restrict__ W,
                       float*       __restrict__ out) {
    extern __shared__ float sh[];
    gemm_tile(g_agg, W + 128 * OUT_DIM, out, blockIdx.x * BM, sh, /*addout=*/true);
}

// ---------------------------------------------------------------------------
// Launch — 6 kernels
// ---------------------------------------------------------------------------
extern "C" void kernel_launch(void* const* d_in, const int* in_sizes, int n_in,
                              void* d_out, int out_size) {
    const float* self_feat = (const float*)d_in[0];
    const float* nbr_feat  = (const float*)d_in[1];
    const int*   src_idx   = (const int*)  d_in[2];
    const float* W         = (const float*)d_in[3];
    float*       out       = (float*)d_out;

    (void)in_sizes; (void)n_in; (void)out_size;

    const int nodes_blks = (N_NODES + 255) / 256;
    const int edges_blks = (N_EDGES + 255) / 256;

    zero_counters_kernel<<<nodes_blks, 256>>>();            // 1
    count_kernel<<<edges_blks, 256>>>(src_idx);             // 2
    scan_partial_kernel<<<N_SCAN_BLKS, SCAN_BLK>>>();       // 3
    scatter_ids_kernel<<<edges_blks, 256>>>(src_idx);       // 4

    cudaFuncSetAttribute(fused_kernel,
                         cudaFuncAttributeMaxDynamicSharedMemorySize, FUSED_SMEM);
    fused_kernel<<<FUSED_GRID, 256, FUSED_SMEM>>>(self_feat, nbr_feat, W, out);  // 5

    cudaFuncSetAttribute(gemm_half1_kernel,
                         cudaFuncAttributeMaxDynamicSharedMemorySize, FUSED_SMEM);
    gemm_half1_kernel<<<N_GEMM_BLKS, 256, FUSED_SMEM>>>(W, out);                 // 6
}